// round 2
// baseline (speedup 1.0000x reference)
#include <cuda_runtime.h>

#define N_NODES 100000
#define N_EDGES 1600000

// Scratch: precomputed P = x @ W1[0:64], Q = x @ W1[64:128]   (25.6 MB each)
__device__ float g_P[N_NODES * 64];
__device__ float g_Q[N_NODES * 64];

// ---------- packed f32x2 helpers (ptxas won't auto-fuse; must come from PTX) ----------
__device__ __forceinline__ unsigned long long pack2(float a, float b) {
    unsigned long long r;
    asm("mov.b64 %0, {%1, %2};" : "=l"(r) : "f"(a), "f"(b));
    return r;
}
__device__ __forceinline__ void unpack2(unsigned long long v, float& a, float& b) {
    asm("mov.b64 {%0, %1}, %2;" : "=f"(a), "=f"(b) : "l"(v));
}
__device__ __forceinline__ unsigned long long ffma2(unsigned long long a, unsigned long long b,
                                                    unsigned long long c) {
    unsigned long long d;
    asm("fma.rn.f32x2 %0, %1, %2, %3;" : "=l"(d) : "l"(a), "l"(b), "l"(c));
    return d;
}
__device__ __forceinline__ unsigned long long fadd2(unsigned long long a, unsigned long long b) {
    unsigned long long d;
    asm("add.rn.f32x2 %0, %1, %2;" : "=l"(d) : "l"(a), "l"(b));
    return d;
}
__device__ __forceinline__ void red4(float* p, float a, float b, float c, float d) {
    asm volatile("red.global.add.v4.f32 [%0], {%1, %2, %3, %4};"
                 :: "l"(p), "f"(a), "f"(b), "f"(c), "f"(d) : "memory");
}

// ---------- zero the output (poisoned 0xAA; atomics accumulate each replay) ----------
__global__ void zero_kernel(float4* __restrict__ out) {
    out[blockIdx.x * 256 + threadIdx.x] = make_float4(0.f, 0.f, 0.f, 0.f);
}

// ---------- node precompute: dst[n][:] = x[n][:] @ Wbase[0:64][:]  ----------
// warp per node; lane owns channel pair (2l, 2l+1); weights register-resident.
__global__ void __launch_bounds__(128) pq_kernel(const float* __restrict__ x,
                                                 const float* __restrict__ Wbase,
                                                 int which) {
    float* dst = which ? g_Q : g_P;
    const int l = threadIdx.x & 31;
    const int warp = (blockIdx.x * 128 + threadIdx.x) >> 5;
    const int nwarps = gridDim.x * 4;

    unsigned long long w[64];
#pragma unroll
    for (int k = 0; k < 64; k++)
        w[k] = *(const unsigned long long*)(Wbase + k * 64 + 2 * l);

    for (int n = warp; n < N_NODES; n += nwarps) {
        const float4* xr = (const float4*)(x + (size_t)n * 64);
        unsigned long long aA = 0ULL, aB = 0ULL;  // {0.f,0.f}
#pragma unroll
        for (int k4 = 0; k4 < 16; k4++) {
            float4 xv = __ldg(xr + k4);
            aA = ffma2(pack2(xv.x, xv.x), w[4 * k4 + 0], aA);
            aB = ffma2(pack2(xv.y, xv.y), w[4 * k4 + 1], aB);
            aA = ffma2(pack2(xv.z, xv.z), w[4 * k4 + 2], aA);
            aB = ffma2(pack2(xv.w, xv.w), w[4 * k4 + 3], aB);
        }
        *(unsigned long long*)(dst + (size_t)n * 64 + 2 * l) = fadd2(aA, aB);
    }
}

// ---------- fused edge kernel ----------
// 4 edges per warp. 8-lane group g = l>>3 owns one edge; lane (octant o = l&7)
// owns channels {4o..4o+3} and {32+4o..32+4o+3} (two separated quads -> every
// weight LDS.128 reads 128B contiguous, conflict-free, 4-way group-broadcast).
__global__ void __launch_bounds__(256) edge_kernel(
    const int* __restrict__ eidx, const float* __restrict__ eattr,
    const float* __restrict__ W1, const float* __restrict__ b1,
    const float* __restrict__ gamma_, const float* __restrict__ beta_,
    const float* __restrict__ W2, const float* __restrict__ b2,
    float* __restrict__ out) {
    __shared__ __align__(16) float sW1c[32][64];  // W1 rows 128..159 (edge_attr part)
    __shared__ __align__(16) float sW2[64][64];
    __shared__ __align__(16) float sb1[64], sg[64], sbt[64], sb2[64];

    const int t = threadIdx.x;
    for (int idx = t; idx < 32 * 64; idx += 256) (&sW1c[0][0])[idx] = W1[128 * 64 + idx];
    for (int idx = t; idx < 64 * 64; idx += 256) (&sW2[0][0])[idx] = W2[idx];
    if (t < 64) { sb1[t] = b1[t]; sg[t] = gamma_[t]; sbt[t] = beta_[t]; sb2[t] = b2[t]; }
    __syncthreads();

    const int warp = (blockIdx.x * 256 + t) >> 5;
    const int ebase = warp * 4;
    if (ebase >= N_EDGES) return;  // uniform per warp

    const int l = t & 31;
    const int g = l >> 3;
    const int o = l & 7;
    const int e = ebase + g;
    const int c0 = 4 * o;
    const int c1 = 32 + 4 * o;
    const unsigned srcbase = (unsigned)(l & 24);

    const int vi = eidx[e];              // edge_index is int32 (JAX x64 disabled)
    const int vj = eidx[N_EDGES + e];
    const float* Pr = g_P + (size_t)vi * 64;
    const float* Qr = g_Q + (size_t)vj * 64;

    float4 p0 = *(const float4*)(Pr + c0);
    float4 p1 = *(const float4*)(Pr + c1);
    float4 q0 = *(const float4*)(Qr + c0);
    float4 q1 = *(const float4*)(Qr + c1);
    float4 bb0 = *(const float4*)(sb1 + c0);
    float4 bb1 = *(const float4*)(sb1 + c1);

    unsigned long long A0 = pack2(p0.x + q0.x + bb0.x, p0.y + q0.y + bb0.y);
    unsigned long long A1 = pack2(p0.z + q0.z + bb0.z, p0.w + q0.w + bb0.w);
    unsigned long long A2 = pack2(p1.x + q1.x + bb1.x, p1.y + q1.y + bb1.y);
    unsigned long long A3 = pack2(p1.z + q1.z + bb1.z, p1.w + q1.w + bb1.w);

    // lane holds eattr[e][4o..4o+3]; full 32-vec shared by group shuffles
    float4 ev4 = __ldg((const float4*)(eattr + (size_t)e * 32) + o);
    float ev[4] = {ev4.x, ev4.y, ev4.z, ev4.w};

    // mm1: acc += eattr @ W1c   (K=32)
#pragma unroll
    for (int k = 0; k < 32; k++) {
        float ek = __shfl_sync(0xffffffffu, ev[k & 3], (int)(srcbase | (unsigned)(k >> 2)));
        unsigned long long ekk = pack2(ek, ek);
        const ulonglong2 w0 = *(const ulonglong2*)(&sW1c[k][c0]);
        const ulonglong2 w1 = *(const ulonglong2*)(&sW1c[k][c1]);
        A0 = ffma2(ekk, w0.x, A0);
        A1 = ffma2(ekk, w0.y, A1);
        A2 = ffma2(ekk, w1.x, A2);
        A3 = ffma2(ekk, w1.y, A3);
    }

    float h[8];
    unpack2(A0, h[0], h[1]); unpack2(A1, h[2], h[3]);
    unpack2(A2, h[4], h[5]); unpack2(A3, h[6], h[7]);

    // LayerNorm over the edge's 64 channels (8 lanes x 8 ch per group)
    float s = 0.f, ss = 0.f;
#pragma unroll
    for (int r = 0; r < 8; r++) { s += h[r]; ss += h[r] * h[r]; }
#pragma unroll
    for (int m = 1; m < 8; m <<= 1) {
        s += __shfl_xor_sync(0xffffffffu, s, m);
        ss += __shfl_xor_sync(0xffffffffu, ss, m);
    }
    const float mu = s * (1.0f / 64.0f);
    const float var = ss * (1.0f / 64.0f) - mu * mu;
    const float rstd = rsqrtf(var + 1e-5f);

    float4 gg0 = *(const float4*)(sg + c0), gg1 = *(const float4*)(sg + c1);
    float4 bt0 = *(const float4*)(sbt + c0), bt1 = *(const float4*)(sbt + c1);
    const float gga[8] = {gg0.x, gg0.y, gg0.z, gg0.w, gg1.x, gg1.y, gg1.z, gg1.w};
    const float bta[8] = {bt0.x, bt0.y, bt0.z, bt0.w, bt1.x, bt1.y, bt1.z, bt1.w};

    // exact GELU: 0.5*v*(1+erf(v/sqrt(2)))
#pragma unroll
    for (int r = 0; r < 8; r++) {
        float v = (h[r] - mu) * rstd * gga[r] + bta[r];
        h[r] = 0.5f * v * (1.0f + erff(v * 0.70710678118654752f));
    }

    // mm2: m = h @ W2 + b2   (K=64)
    float4 b20 = *(const float4*)(sb2 + c0), b21 = *(const float4*)(sb2 + c1);
    unsigned long long M0 = pack2(b20.x, b20.y);
    unsigned long long M1 = pack2(b20.z, b20.w);
    unsigned long long M2 = pack2(b21.x, b21.y);
    unsigned long long M3 = pack2(b21.z, b21.w);

#pragma unroll
    for (int c = 0; c < 32; c++) {
        float hc = __shfl_sync(0xffffffffu, h[c & 3], (int)(srcbase | (unsigned)(c >> 2)));
        unsigned long long hcc = pack2(hc, hc);
        const ulonglong2 w0 = *(const ulonglong2*)(&sW2[c][c0]);
        const ulonglong2 w1 = *(const ulonglong2*)(&sW2[c][c1]);
        M0 = ffma2(hcc, w0.x, M0);
        M1 = ffma2(hcc, w0.y, M1);
        M2 = ffma2(hcc, w1.x, M2);
        M3 = ffma2(hcc, w1.y, M3);
    }
#pragma unroll
    for (int c = 32; c < 64; c++) {
        float hc = __shfl_sync(0xffffffffu, h[4 + (c & 3)], (int)(srcbase | (unsigned)((c - 32) >> 2)));
        unsigned long long hcc = pack2(hc, hc);
        const ulonglong2 w0 = *(const ulonglong2*)(&sW2[c][c0]);
        const ulonglong2 w1 = *(const ulonglong2*)(&sW2[c][c1]);
        M0 = ffma2(hcc, w0.x, M0);
        M1 = ffma2(hcc, w0.y, M1);
        M2 = ffma2(hcc, w1.x, M2);
        M3 = ffma2(hcc, w1.y, M3);
    }

    float m[8];
    unpack2(M0, m[0], m[1]); unpack2(M1, m[2], m[3]);
    unpack2(M2, m[4], m[5]); unpack2(M3, m[6], m[7]);

    float* op = out + (size_t)vj * 64;
    red4(op + c0, m[0], m[1], m[2], m[3]);
    red4(op + c1, m[4], m[5], m[6], m[7]);
}

extern "C" void kernel_launch(void* const* d_in, const int* in_sizes, int n_in,
                              void* d_out, int out_size) {
    const float* x = (const float*)d_in[0];
    const int* eidx = (const int*)d_in[1];   // int32 (JAX default, no x64)
    const float* eattr = (const float*)d_in[2];
    const float* W1 = (const float*)d_in[3];
    const float* b1 = (const float*)d_in[4];
    const float* gamma_ = (const float*)d_in[5];
    const float* beta_ = (const float*)d_in[6];
    const float* W2 = (const float*)d_in[7];
    const float* b2 = (const float*)d_in[8];
    float* out = (float*)d_out;

    // out = 100000*64 floats = 1.6M float4 -> 6250 blocks x 256 exactly
    zero_kernel<<<6250, 256>>>((float4*)out);

    pq_kernel<<<1024, 128>>>(x, W1, 0);            // P from W1 rows 0..63
    pq_kernel<<<1024, 128>>>(x, W1 + 64 * 64, 1);  // Q from W1 rows 64..127

    // 1.6M edges / 4 per warp = 400K warps / 8 per CTA = 50000 CTAs (exact)
    edge_kernel<<<50000, 256>>>(eidx, eattr, W1, b1, gamma_, beta_, W2, b2, out);
}

// round 3
// speedup vs baseline: 1.7973x; 1.7973x over previous
#include <cuda_runtime.h>

#define N_NODES 100000
#define N_EDGES 1600000

// Scratch: precomputed P = x @ W1[0:64], Q = x @ W1[64:128]
__device__ float g_P[N_NODES * 64];
__device__ float g_Q[N_NODES * 64];

// ---------- packed f32x2 helpers ----------
__device__ __forceinline__ unsigned long long pack2(float a, float b) {
    unsigned long long r;
    asm("mov.b64 %0, {%1, %2};" : "=l"(r) : "f"(a), "f"(b));
    return r;
}
__device__ __forceinline__ void unpack2(unsigned long long v, float& a, float& b) {
    asm("mov.b64 {%0, %1}, %2;" : "=f"(a), "=f"(b) : "l"(v));
}
__device__ __forceinline__ unsigned long long ffma2(unsigned long long a, unsigned long long b,
                                                    unsigned long long c) {
    unsigned long long d;
    asm("fma.rn.f32x2 %0, %1, %2, %3;" : "=l"(d) : "l"(a), "l"(b), "l"(c));
    return d;
}
__device__ __forceinline__ unsigned long long fadd2(unsigned long long a, unsigned long long b) {
    unsigned long long d;
    asm("add.rn.f32x2 %0, %1, %2;" : "=l"(d) : "l"(a), "l"(b));
    return d;
}
__device__ __forceinline__ void red4(float* p, float a, float b, float c, float d) {
    asm volatile("red.global.add.v4.f32 [%0], {%1, %2, %3, %4};"
                 :: "l"(p), "f"(a), "f"(b), "f"(c), "f"(d) : "memory");
}

// ---------- zero the output ----------
__global__ void zero_kernel(float4* __restrict__ out) {
    out[blockIdx.x * 256 + threadIdx.x] = make_float4(0.f, 0.f, 0.f, 0.f);
}

// ---------- node precompute ----------
__global__ void __launch_bounds__(128) pq_kernel(const float* __restrict__ x,
                                                 const float* __restrict__ Wbase,
                                                 int which) {
    float* dst = which ? g_Q : g_P;
    const int l = threadIdx.x & 31;
    const int warp = (blockIdx.x * 128 + threadIdx.x) >> 5;
    const int nwarps = gridDim.x * 4;

    unsigned long long w[64];
#pragma unroll
    for (int k = 0; k < 64; k++)
        w[k] = *(const unsigned long long*)(Wbase + k * 64 + 2 * l);

    for (int n = warp; n < N_NODES; n += nwarps) {
        const float4* xr = (const float4*)(x + (size_t)n * 64);
        unsigned long long aA = 0ULL, aB = 0ULL;
#pragma unroll
        for (int k4 = 0; k4 < 16; k4++) {
            float4 xv = __ldg(xr + k4);
            aA = ffma2(pack2(xv.x, xv.x), w[4 * k4 + 0], aA);
            aB = ffma2(pack2(xv.y, xv.y), w[4 * k4 + 1], aB);
            aA = ffma2(pack2(xv.z, xv.z), w[4 * k4 + 2], aA);
            aB = ffma2(pack2(xv.w, xv.w), w[4 * k4 + 3], aB);
        }
        *(unsigned long long*)(dst + (size_t)n * 64 + 2 * l) = fadd2(aA, aB);
    }
}

// ---------- fused edge kernel: smem-tiled, 256 edges/CTA, thread tile 8e x 8ch ----------
// Thread layout: tr = tid>>3 (edge group, 8 edges), tc = tid&7 (channel group, 8 ch).
// Activations staged transposed [k][256 edges], XOR-swizzled 32B chunks: ec ^= (k>>3).
// Dynamic smem layout (bytes):
//   0      : sH     float[64*256]  (65536)  rows 0..31 double as eattrT during GEMM1
//   65536  : sW1c   float[32*64]   (8192)
//   73728  : sW2    float[64*64]   (16384)
//   90112  : sIi    int[256]       (1024)
//   91136  : sIj    int[256]       (1024)
//   92160  : sB1,sB2,sG,sBt float[64] each (1024)
#define SMEM_BYTES 93184

__global__ void __launch_bounds__(256, 2) edge_kernel(
    const int* __restrict__ eidx, const float* __restrict__ eattr,
    const float* __restrict__ W1, const float* __restrict__ b1,
    const float* __restrict__ gamma_, const float* __restrict__ beta_,
    const float* __restrict__ W2, const float* __restrict__ b2,
    float* __restrict__ out) {
    extern __shared__ __align__(16) char smem[];
    float* sH   = (float*)smem;              // [64][256] swizzled
    float* sW1c = (float*)(smem + 65536);    // [32][64]
    float* sW2  = (float*)(smem + 73728);    // [64][64]
    int*   sIi  = (int*)(smem + 90112);
    int*   sIj  = (int*)(smem + 91136);
    float* sB1  = (float*)(smem + 92160);
    float* sB2  = sB1 + 64;
    float* sG   = sB1 + 128;
    float* sBt  = sB1 + 192;

    const int t = threadIdx.x;
    const int tr = t >> 3;      // 0..31
    const int tc = t & 7;       // 0..7
    const int Eb = blockIdx.x * 256;
    const int lane = t & 31;
    const unsigned grpbase = (unsigned)(lane & 24);  // 8-lane group base (same tr)

    // ---- Stage A: cooperative loads ----
    sIi[t] = eidx[Eb + t];
    sIj[t] = eidx[N_EDGES + Eb + t];
    {
        const float4* w1s = (const float4*)(W1 + 128 * 64);
#pragma unroll
        for (int i = 0; i < 2; i++) ((float4*)sW1c)[t + 256 * i] = w1s[t + 256 * i];
        const float4* w2s = (const float4*)W2;
#pragma unroll
        for (int i = 0; i < 4; i++) ((float4*)sW2)[t + 256 * i] = w2s[t + 256 * i];
        if (t < 64) { sB1[t] = b1[t]; sB2[t] = b2[t]; sG[t] = gamma_[t]; sBt[t] = beta_[t]; }
    }
    // edge-attr transpose: thread t owns edge Eb+t; write [k][t] swizzled
    {
        const float4* er = (const float4*)(eattr + (size_t)(Eb + t) * 32);
        float4 ev[8];
#pragma unroll
        for (int i = 0; i < 8; i++) ev[i] = __ldg(er + i);
        const float* evf = (const float*)ev;
        const int ecbase = t >> 3, off = t & 7;
#pragma unroll
        for (int k = 0; k < 32; k++) {
            sH[k * 256 + ((ecbase ^ (k >> 3)) & 31) * 8 + off] = evf[k];
        }
    }
    __syncthreads();

    // ---- accumulators: 8 edges x 8 ch as ULL[8][4] ----
    unsigned long long acc[8][4];

    // ---- init acc = P[vi] + Q[vj] + b1 ----
    {
        float4 b1a = *(const float4*)(sB1 + tc * 8);
        float4 b1b = *(const float4*)(sB1 + tc * 8 + 4);
#pragma unroll
        for (int e = 0; e < 8; e++) {
            const int vi = sIi[tr * 8 + e];
            const int vj = sIj[tr * 8 + e];
            const float* Pr = g_P + (size_t)vi * 64 + tc * 8;
            const float* Qr = g_Q + (size_t)vj * 64 + tc * 8;
            float4 pa = *(const float4*)Pr;
            float4 pb = *(const float4*)(Pr + 4);
            float4 qa = *(const float4*)Qr;
            float4 qb = *(const float4*)(Qr + 4);
            acc[e][0] = pack2(pa.x + qa.x + b1a.x, pa.y + qa.y + b1a.y);
            acc[e][1] = pack2(pa.z + qa.z + b1a.z, pa.w + qa.w + b1a.w);
            acc[e][2] = pack2(pb.x + qb.x + b1b.x, pb.y + qb.y + b1b.y);
            acc[e][3] = pack2(pb.z + qb.z + b1b.z, pb.w + qb.w + b1b.w);
        }
    }

    // ---- GEMM1: acc += eattrT(k x 256) outer W1c(k x 64), K=32 ----
#pragma unroll
    for (int k = 0; k < 32; k++) {
        const float* arow = sH + k * 256 + ((tr ^ (k >> 3)) & 31) * 8;
        float4 a0 = *(const float4*)arow;
        float4 a1 = *(const float4*)(arow + 4);
        const ulonglong2 w0 = *(const ulonglong2*)(sW1c + k * 64 + tc * 8);
        const ulonglong2 w1 = *(const ulonglong2*)(sW1c + k * 64 + tc * 8 + 4);
        const float a[8] = {a0.x, a0.y, a0.z, a0.w, a1.x, a1.y, a1.z, a1.w};
#pragma unroll
        for (int e = 0; e < 8; e++) {
            unsigned long long ae = pack2(a[e], a[e]);
            acc[e][0] = ffma2(ae, w0.x, acc[e][0]);
            acc[e][1] = ffma2(ae, w0.y, acc[e][1]);
            acc[e][2] = ffma2(ae, w1.x, acc[e][2]);
            acc[e][3] = ffma2(ae, w1.y, acc[e][3]);
        }
    }

    // ---- LayerNorm stats: rows live across the 8 lanes sharing tr ----
    float s[8], ss[8];
#pragma unroll
    for (int e = 0; e < 8; e++) {
        float h0, h1, h2, h3, h4, h5, h6, h7;
        unpack2(acc[e][0], h0, h1); unpack2(acc[e][1], h2, h3);
        unpack2(acc[e][2], h4, h5); unpack2(acc[e][3], h6, h7);
        s[e]  = ((h0 + h1) + (h2 + h3)) + ((h4 + h5) + (h6 + h7));
        ss[e] = ((h0*h0 + h1*h1) + (h2*h2 + h3*h3)) + ((h4*h4 + h5*h5) + (h6*h6 + h7*h7));
    }
#pragma unroll
    for (int m = 1; m < 8; m <<= 1) {
#pragma unroll
        for (int e = 0; e < 8; e++) {
            s[e]  += __shfl_xor_sync(0xffffffffu, s[e], m);
            ss[e] += __shfl_xor_sync(0xffffffffu, ss[e], m);
        }
    }

    float4 ga = *(const float4*)(sG + tc * 8);
    float4 gb = *(const float4*)(sG + tc * 8 + 4);
    float4 ba = *(const float4*)(sBt + tc * 8);
    float4 bb = *(const float4*)(sBt + tc * 8 + 4);
    const float gg[8] = {ga.x, ga.y, ga.z, ga.w, gb.x, gb.y, gb.z, gb.w};
    const float bt[8] = {ba.x, ba.y, ba.z, ba.w, bb.x, bb.y, bb.z, bb.w};

    __syncthreads();  // all GEMM1 reads of eattrT done before hT overwrites rows 0..31

    // ---- normalize + GELU + store hT transposed (swizzled) ----
#pragma unroll
    for (int e = 0; e < 8; e++) {
        const float mu = s[e] * (1.0f / 64.0f);
        const float var = ss[e] * (1.0f / 64.0f) - mu * mu;
        const float rstd = rsqrtf(var + 1e-5f);
        float h[8];
        unpack2(acc[e][0], h[0], h[1]); unpack2(acc[e][1], h[2], h[3]);
        unpack2(acc[e][2], h[4], h[5]); unpack2(acc[e][3], h[6], h[7]);
#pragma unroll
        for (int c = 0; c < 8; c++) {
            float v = (h[c] - mu) * rstd * gg[c] + bt[c];
            h[c] = 0.5f * v * (1.0f + erff(v * 0.70710678118654752f));
        }
        // write row = tc*8+c, edges tr*8..tr*8+7  (row>>3 == tc)
#pragma unroll
        for (int c = 0; c < 8; c++) {
            // reuse h as per-row scratch: we need column writes; gather per row below
            // (handled outside: store h[c] at [tc*8+c][edge tr*8+e])
            sH[(tc * 8 + c) * 256 + ((tr ^ tc) & 31) * 8 + e] = h[c];
        }
    }
    __syncthreads();

    // ---- GEMM2: m = h(256 x 64) @ W2(64 x 64) + b2, K=64 ----
    {
        float4 b2a = *(const float4*)(sB2 + tc * 8);
        float4 b2b = *(const float4*)(sB2 + tc * 8 + 4);
#pragma unroll
        for (int e = 0; e < 8; e++) {
            acc[e][0] = pack2(b2a.x, b2a.y);
            acc[e][1] = pack2(b2a.z, b2a.w);
            acc[e][2] = pack2(b2b.x, b2b.y);
            acc[e][3] = pack2(b2b.z, b2b.w);
        }
    }
#pragma unroll
    for (int k = 0; k < 64; k++) {
        const float* arow = sH + k * 256 + ((tr ^ (k >> 3)) & 31) * 8;
        float4 a0 = *(const float4*)arow;
        float4 a1 = *(const float4*)(arow + 4);
        const ulonglong2 w0 = *(const ulonglong2*)(sW2 + k * 64 + tc * 8);
        const ulonglong2 w1 = *(const ulonglong2*)(sW2 + k * 64 + tc * 8 + 4);
        const float a[8] = {a0.x, a0.y, a0.z, a0.w, a1.x, a1.y, a1.z, a1.w};
#pragma unroll
        for (int e = 0; e < 8; e++) {
            unsigned long long ae = pack2(a[e], a[e]);
            acc[e][0] = ffma2(ae, w0.x, acc[e][0]);
            acc[e][1] = ffma2(ae, w0.y, acc[e][1]);
            acc[e][2] = ffma2(ae, w1.x, acc[e][2]);
            acc[e][3] = ffma2(ae, w1.y, acc[e][3]);
        }
    }

    // ---- scatter-add ----
#pragma unroll
    for (int e = 0; e < 8; e++) {
        const int vj = sIj[tr * 8 + e];
        float* op = out + (size_t)vj * 64 + tc * 8;
        float m0, m1, m2, m3, m4, m5, m6, m7;
        unpack2(acc[e][0], m0, m1); unpack2(acc[e][1], m2, m3);
        unpack2(acc[e][2], m4, m5); unpack2(acc[e][3], m6, m7);
        red4(op, m0, m1, m2, m3);
        red4(op + 4, m4, m5, m6, m7);
    }
}

extern "C" void kernel_launch(void* const* d_in, const int* in_sizes, int n_in,
                              void* d_out, int out_size) {
    const float* x = (const float*)d_in[0];
    const int* eidx = (const int*)d_in[1];
    const float* eattr = (const float*)d_in[2];
    const float* W1 = (const float*)d_in[3];
    const float* b1 = (const float*)d_in[4];
    const float* gamma_ = (const float*)d_in[5];
    const float* beta_ = (const float*)d_in[6];
    const float* W2 = (const float*)d_in[7];
    const float* b2 = (const float*)d_in[8];
    float* out = (float*)d_out;

    static int smem_set = 0;
    if (!smem_set) {
        cudaFuncSetAttribute(edge_kernel, cudaFuncAttributeMaxDynamicSharedMemorySize,
                             SMEM_BYTES);
        smem_set = 1;
    }

    zero_kernel<<<6250, 256>>>((float4*)out);
    pq_kernel<<<1024, 128>>>(x, W1, 0);
    pq_kernel<<<1024, 128>>>(x, W1 + 64 * 64, 1);
    edge_kernel<<<6250, 256, SMEM_BYTES>>>(eidx, eattr, W1, b1, gamma_, beta_, W2, b2, out);
}